// round 5
// baseline (speedup 1.0000x reference)
#include <cuda_runtime.h>
#include <cuda_fp16.h>

#define N_NODES 50000
#define N_EDGES 800000
#define EMB     100
#define EPSN    1e-12f
#define FULL    0xffffffffu

// Scratch (allocation-free rule: __device__ globals)
__device__ __half g_embH[N_NODES * EMB];
__device__ __half g_bufHA[N_NODES * EMB];
__device__ __half g_bufHB[N_NODES * EMB];
__device__ int    g_deg[N_NODES];
__device__ int    g_rank[N_EDGES];
__device__ int    g_rowptr[N_NODES];
__device__ int    g_counter;
__device__ int2   g_cells[N_EDGES];       // {col, val-as-int-bits}

// ---------------------------------------------------------------------------
// Layer 0: out = a0 * normalize(emb); embH = fp16(emb); zero deg/counter.
// One warp per row (lanes 0..24 each own 4 dims).
// ---------------------------------------------------------------------------
__global__ void __launch_bounds__(256)
norm0_kernel(const float* __restrict__ emb, float* __restrict__ out,
             __half* __restrict__ embh, const float* __restrict__ a,
             int* __restrict__ deg, int* __restrict__ counter)
{
    int t = blockIdx.x * blockDim.x + threadIdx.x;
    if (t < N_NODES) deg[t] = 0;
    if (t == 0) *counter = 0;

    int warp = t >> 5;
    int lane = t & 31;
    if (warp >= N_NODES) return;

    float4 v = make_float4(0.f, 0.f, 0.f, 0.f);
    if (lane < 25) v = __ldg((const float4*)(emb + (size_t)warp * EMB) + lane);

    float ss = v.x * v.x + v.y * v.y + v.z * v.z + v.w * v.w;
#pragma unroll
    for (int o = 16; o; o >>= 1) ss += __shfl_xor_sync(FULL, ss, o);

    float scale = __ldg(a) / fmaxf(sqrtf(ss), EPSN);

    if (lane < 25) {
        float4 o;
        o.x = v.x * scale; o.y = v.y * scale; o.z = v.z * scale; o.w = v.w * scale;
        ((float4*)(out + (size_t)warp * EMB))[lane] = o;

        __half2 h0 = __floats2half2_rn(v.x, v.y);
        __half2 h1 = __floats2half2_rn(v.z, v.w);
        uint2 u;
        u.x = *(unsigned*)&h0; u.y = *(unsigned*)&h1;
        ((uint2*)(embh + (size_t)warp * EMB))[lane] = u;
    }
}

// ---------------------------------------------------------------------------
// CSR build: histogram that also records each edge's rank within its row,
// then warp-aggregated atomic offsets, then an atomic-free scatter (4 edges
// per thread for MLP on the rowptr gather chain).
// ---------------------------------------------------------------------------
__global__ void hist_rank_kernel(const int* __restrict__ rows,
                                 int* __restrict__ deg, int* __restrict__ rank)
{
    int e = blockIdx.x * blockDim.x + threadIdx.x;
    if (e < N_EDGES) rank[e] = atomicAdd(&deg[rows[e]], 1);
}

__global__ void offsets_kernel(const int* __restrict__ deg, int* __restrict__ rowptr,
                               int* __restrict__ counter)
{
    int i = blockIdx.x * blockDim.x + threadIdx.x;
    int lane = threadIdx.x & 31;
    int d = (i < N_NODES) ? deg[i] : 0;

    int s = d;                                   // warp inclusive scan
#pragma unroll
    for (int o = 1; o < 32; o <<= 1) {
        int t = __shfl_up_sync(FULL, s, o);
        if (lane >= o) s += t;
    }
    int total = __shfl_sync(FULL, s, 31);
    int base = 0;
    if (lane == 31) base = atomicAdd(counter, total);
    base = __shfl_sync(FULL, base, 31);
    if (i < N_NODES) rowptr[i] = base + s - d;   // exclusive within warp
}

__global__ void __launch_bounds__(256)
scatter_kernel(const int* __restrict__ rows, const int* __restrict__ cols,
               const float* __restrict__ vals, const int* __restrict__ rowptr,
               const int* __restrict__ rank, int2* __restrict__ cells)
{
    int base = (blockIdx.x * blockDim.x) * 4 + threadIdx.x;
    int e[4], r[4], rk[4];
    bool ok[4];
#pragma unroll
    for (int k = 0; k < 4; k++) {
        e[k] = base + k * 256;
        ok[k] = e[k] < N_EDGES;
        r[k]  = ok[k] ? __ldg(rows + e[k]) : 0;
        rk[k] = ok[k] ? __ldg(rank + e[k]) : 0;
    }
    int pos[4];
#pragma unroll
    for (int k = 0; k < 4; k++)
        pos[k] = ok[k] ? (__ldg(rowptr + r[k]) + rk[k]) : 0;   // 4 independent gathers
#pragma unroll
    for (int k = 0; k < 4; k++) {
        if (ok[k])
            cells[pos[k]] = make_int2(__ldg(cols + e[k]),
                                      __float_as_int(__ldg(vals + e[k])));
    }
}

// ---------------------------------------------------------------------------
// Fused SpMM + normalize + accumulate. Warp per row.
// Direct per-lane cell loads (broadcast), unrolled x4 -> 4 independent
// gather chains per iteration (MLP=4), no shuffles in the hot loop.
// ---------------------------------------------------------------------------
template<bool WRITE_NEXT>
__global__ void __launch_bounds__(256)
spmm_fused_kernel(const int* __restrict__ rowptr, const int* __restrict__ deg,
                  const int2* __restrict__ cells, const __half* __restrict__ xh,
                  __half* __restrict__ yh, float* __restrict__ out,
                  const float* __restrict__ a, int layer)
{
    int warp = (blockIdx.x * blockDim.x + threadIdx.x) >> 5;
    int lane = threadIdx.x & 31;
    if (warp >= N_NODES) return;

    int p   = __ldg(rowptr + warp);
    int end = p + __ldg(deg + warp);

    float4 acc = make_float4(0.f, 0.f, 0.f, 0.f);
    bool act = lane < 25;

    for (; p + 3 < end; p += 4) {
        int2 cv0 = __ldg(cells + p);
        int2 cv1 = __ldg(cells + p + 1);
        int2 cv2 = __ldg(cells + p + 2);
        int2 cv3 = __ldg(cells + p + 3);
        if (act) {
            uint2 u0 = __ldg((const uint2*)(xh + (size_t)cv0.x * EMB) + lane);
            uint2 u1 = __ldg((const uint2*)(xh + (size_t)cv1.x * EMB) + lane);
            uint2 u2 = __ldg((const uint2*)(xh + (size_t)cv2.x * EMB) + lane);
            uint2 u3 = __ldg((const uint2*)(xh + (size_t)cv3.x * EMB) + lane);
            float w0 = __int_as_float(cv0.y), w1 = __int_as_float(cv1.y);
            float w2 = __int_as_float(cv2.y), w3 = __int_as_float(cv3.y);
            float2 l0 = __half22float2(*(__half2*)&u0.x), h0 = __half22float2(*(__half2*)&u0.y);
            float2 l1 = __half22float2(*(__half2*)&u1.x), h1 = __half22float2(*(__half2*)&u1.y);
            float2 l2 = __half22float2(*(__half2*)&u2.x), h2 = __half22float2(*(__half2*)&u2.y);
            float2 l3 = __half22float2(*(__half2*)&u3.x), h3 = __half22float2(*(__half2*)&u3.y);
            acc.x += w0 * l0.x; acc.y += w0 * l0.y; acc.z += w0 * h0.x; acc.w += w0 * h0.y;
            acc.x += w1 * l1.x; acc.y += w1 * l1.y; acc.z += w1 * h1.x; acc.w += w1 * h1.y;
            acc.x += w2 * l2.x; acc.y += w2 * l2.y; acc.z += w2 * h2.x; acc.w += w2 * h2.y;
            acc.x += w3 * l3.x; acc.y += w3 * l3.y; acc.z += w3 * h3.x; acc.w += w3 * h3.y;
        }
    }
    for (; p < end; p++) {
        int2 cv = __ldg(cells + p);
        if (act) {
            uint2 u = __ldg((const uint2*)(xh + (size_t)cv.x * EMB) + lane);
            float w = __int_as_float(cv.y);
            float2 lo = __half22float2(*(__half2*)&u.x);
            float2 hi = __half22float2(*(__half2*)&u.y);
            acc.x += w * lo.x; acc.y += w * lo.y;
            acc.z += w * hi.x; acc.w += w * hi.y;
        }
    }

    // normalize + accumulate (full row lives in the warp's registers)
    float ss = acc.x * acc.x + acc.y * acc.y + acc.z * acc.z + acc.w * acc.w;
#pragma unroll
    for (int o = 16; o; o >>= 1) ss += __shfl_xor_sync(FULL, ss, o);

    float scale = __ldg(a + layer) / fmaxf(sqrtf(ss), EPSN);

    if (act) {
        if (WRITE_NEXT) {
            __half2 h0 = __floats2half2_rn(acc.x, acc.y);
            __half2 h1 = __floats2half2_rn(acc.z, acc.w);
            uint2 u;
            u.x = *(unsigned*)&h0; u.y = *(unsigned*)&h1;
            ((uint2*)(yh + (size_t)warp * EMB))[lane] = u;
        }
        float4* orow = (float4*)(out + (size_t)warp * EMB);
        float4 pv = orow[lane];
        pv.x += scale * acc.x; pv.y += scale * acc.y;
        pv.z += scale * acc.z; pv.w += scale * acc.w;
        orow[lane] = pv;
    }
}

// ---------------------------------------------------------------------------
// Launch: inputs are adj_row, adj_col, adj_val, embedding, a
// ---------------------------------------------------------------------------
extern "C" void kernel_launch(void* const* d_in, const int* in_sizes, int n_in,
                              void* d_out, int out_size)
{
    const int*   adj_row = (const int*)  d_in[0];
    const int*   adj_col = (const int*)  d_in[1];
    const float* adj_val = (const float*)d_in[2];
    const float* emb     = (const float*)d_in[3];
    const float* a       = (const float*)d_in[4];
    float*       out     = (float*)d_out;

    __half* embh; cudaGetSymbolAddress((void**)&embh, g_embH);
    __half* bufA; cudaGetSymbolAddress((void**)&bufA, g_bufHA);
    __half* bufB; cudaGetSymbolAddress((void**)&bufB, g_bufHB);
    int*   deg;   cudaGetSymbolAddress((void**)&deg,   g_deg);
    int*   rank;  cudaGetSymbolAddress((void**)&rank,  g_rank);
    int*   rp;    cudaGetSymbolAddress((void**)&rp,    g_rowptr);
    int*   cnt;   cudaGetSymbolAddress((void**)&cnt,   g_counter);
    int2*  cells; cudaGetSymbolAddress((void**)&cells, g_cells);

    const int EB   = (N_EDGES + 255) / 256;
    const int EB4  = (N_EDGES + 1023) / 1024;       // 4 edges/thread
    const int ROWB = (N_NODES * 32 + 255) / 256;
    const int NODB = (N_NODES + 255) / 256;

    // layer 0 + init
    norm0_kernel<<<ROWB, 256>>>(emb, out, embh, a, deg, cnt);
    // CSR build (rank trick: no atomics in scatter)
    hist_rank_kernel<<<EB, 256>>>(adj_row, deg, rank);
    offsets_kernel<<<NODB, 256>>>(deg, rp, cnt);
    scatter_kernel<<<EB4, 256>>>(adj_row, adj_col, adj_val, rp, rank, cells);
    // 3 fused SpMM + normalize + accumulate layers
    spmm_fused_kernel<true ><<<ROWB, 256>>>(rp, deg, cells, embh, bufA, out, a, 1);
    spmm_fused_kernel<true ><<<ROWB, 256>>>(rp, deg, cells, bufA, bufB, out, a, 2);
    spmm_fused_kernel<false><<<ROWB, 256>>>(rp, deg, cells, bufB, nullptr, out, a, 3);
}

// round 6
// speedup vs baseline: 1.3374x; 1.3374x over previous
#include <cuda_runtime.h>
#include <cuda_fp16.h>

#define N_NODES 50000
#define N_EDGES 800000
#define EMB     100
#define EPSN    1e-12f
#define FULL    0xffffffffu

// Scratch (allocation-free rule: __device__ globals)
__device__ __half g_embH[N_NODES * EMB];
__device__ __half g_bufHA[N_NODES * EMB];
__device__ __half g_bufHB[N_NODES * EMB];
__device__ int    g_deg[N_NODES];
__device__ int    g_rank[N_EDGES];
__device__ int    g_rowptr[N_NODES];
__device__ int    g_counter;
__device__ int2   g_cells[N_EDGES];       // {col, val-as-int-bits}

// ---------------------------------------------------------------------------
// Layer 0: out = a0 * normalize(emb); embH = fp16(emb); zero deg/counter.
// One warp per row (lanes 0..24 each own 4 dims).
// ---------------------------------------------------------------------------
__global__ void __launch_bounds__(256)
norm0_kernel(const float* __restrict__ emb, float* __restrict__ out,
             __half* __restrict__ embh, const float* __restrict__ a,
             int* __restrict__ deg, int* __restrict__ counter)
{
    int t = blockIdx.x * blockDim.x + threadIdx.x;
    if (t < N_NODES) deg[t] = 0;
    if (t == 0) *counter = 0;

    int warp = t >> 5;
    int lane = t & 31;
    if (warp >= N_NODES) return;

    float4 v = make_float4(0.f, 0.f, 0.f, 0.f);
    if (lane < 25) v = __ldg((const float4*)(emb + (size_t)warp * EMB) + lane);

    float ss = v.x * v.x + v.y * v.y + v.z * v.z + v.w * v.w;
#pragma unroll
    for (int o = 16; o; o >>= 1) ss += __shfl_xor_sync(FULL, ss, o);

    float scale = __ldg(a) / fmaxf(sqrtf(ss), EPSN);

    if (lane < 25) {
        float4 o;
        o.x = v.x * scale; o.y = v.y * scale; o.z = v.z * scale; o.w = v.w * scale;
        ((float4*)(out + (size_t)warp * EMB))[lane] = o;

        __half2 h0 = __floats2half2_rn(v.x, v.y);
        __half2 h1 = __floats2half2_rn(v.z, v.w);
        uint2 u;
        u.x = *(unsigned*)&h0; u.y = *(unsigned*)&h1;
        ((uint2*)(embh + (size_t)warp * EMB))[lane] = u;
    }
}

// ---------------------------------------------------------------------------
// CSR build: histogram recording each edge's rank within its row, then
// warp-aggregated atomic offsets, then atomic-free scatter (1 edge/thread —
// measured faster than 4/thread: latency hiding comes from warp count here).
// ---------------------------------------------------------------------------
__global__ void hist_rank_kernel(const int* __restrict__ rows,
                                 int* __restrict__ deg, int* __restrict__ rank)
{
    int e = blockIdx.x * blockDim.x + threadIdx.x;
    if (e < N_EDGES) rank[e] = atomicAdd(&deg[rows[e]], 1);
}

__global__ void offsets_kernel(const int* __restrict__ deg, int* __restrict__ rowptr,
                               int* __restrict__ counter)
{
    int i = blockIdx.x * blockDim.x + threadIdx.x;
    int lane = threadIdx.x & 31;
    int d = (i < N_NODES) ? deg[i] : 0;

    int s = d;                                   // warp inclusive scan
#pragma unroll
    for (int o = 1; o < 32; o <<= 1) {
        int t = __shfl_up_sync(FULL, s, o);
        if (lane >= o) s += t;
    }
    int total = __shfl_sync(FULL, s, 31);
    int base = 0;
    if (lane == 31) base = atomicAdd(counter, total);
    base = __shfl_sync(FULL, base, 31);
    if (i < N_NODES) rowptr[i] = base + s - d;   // exclusive within warp
}

__global__ void scatter_kernel(const int* __restrict__ rows,
                               const int* __restrict__ cols,
                               const float* __restrict__ vals,
                               const int* __restrict__ rowptr,
                               const int* __restrict__ rank,
                               int2* __restrict__ cells)
{
    int e = blockIdx.x * blockDim.x + threadIdx.x;
    if (e >= N_EDGES) return;
    int r = __ldg(rows + e);
    int pos = __ldg(rowptr + r) + __ldg(rank + e);
    cells[pos] = make_int2(__ldg(cols + e), __float_as_int(__ldg(vals + e)));
}

// ---------------------------------------------------------------------------
// Fused SpMM + normalize + accumulate. Warp per row. (R3 best variant:
// direct per-lane cell loads, unroll x2 -> 2 independent gather chains.)
// ---------------------------------------------------------------------------
template<bool WRITE_NEXT>
__global__ void __launch_bounds__(256)
spmm_fused_kernel(const int* __restrict__ rowptr, const int* __restrict__ deg,
                  const int2* __restrict__ cells, const __half* __restrict__ xh,
                  __half* __restrict__ yh, float* __restrict__ out,
                  const float* __restrict__ a, int layer)
{
    int warp = (blockIdx.x * blockDim.x + threadIdx.x) >> 5;
    int lane = threadIdx.x & 31;
    if (warp >= N_NODES) return;

    int p   = __ldg(rowptr + warp);
    int end = p + __ldg(deg + warp);

    float4 acc = make_float4(0.f, 0.f, 0.f, 0.f);
    bool act = lane < 25;

    for (; p + 1 < end; p += 2) {
        int2 cv0 = __ldg(cells + p);
        int2 cv1 = __ldg(cells + p + 1);
        if (act) {
            uint2 u0 = __ldg((const uint2*)(xh + (size_t)cv0.x * EMB) + lane);
            uint2 u1 = __ldg((const uint2*)(xh + (size_t)cv1.x * EMB) + lane);
            float w0 = __int_as_float(cv0.y);
            float w1 = __int_as_float(cv1.y);
            float2 p0 = __half22float2(*(__half2*)&u0.x);
            float2 q0 = __half22float2(*(__half2*)&u0.y);
            float2 p1 = __half22float2(*(__half2*)&u1.x);
            float2 q1 = __half22float2(*(__half2*)&u1.y);
            acc.x += w0 * p0.x; acc.y += w0 * p0.y;
            acc.z += w0 * q0.x; acc.w += w0 * q0.y;
            acc.x += w1 * p1.x; acc.y += w1 * p1.y;
            acc.z += w1 * q1.x; acc.w += w1 * q1.y;
        }
    }
    if (p < end) {
        int2 cv = __ldg(cells + p);
        if (act) {
            uint2 u = __ldg((const uint2*)(xh + (size_t)cv.x * EMB) + lane);
            float w = __int_as_float(cv.y);
            float2 pp = __half22float2(*(__half2*)&u.x);
            float2 qq = __half22float2(*(__half2*)&u.y);
            acc.x += w * pp.x; acc.y += w * pp.y;
            acc.z += w * qq.x; acc.w += w * qq.y;
        }
    }

    // normalize + accumulate (full row lives in the warp's registers)
    float ss = acc.x * acc.x + acc.y * acc.y + acc.z * acc.z + acc.w * acc.w;
#pragma unroll
    for (int o = 16; o; o >>= 1) ss += __shfl_xor_sync(FULL, ss, o);

    float scale = __ldg(a + layer) / fmaxf(sqrtf(ss), EPSN);

    if (act) {
        if (WRITE_NEXT) {
            __half2 h0 = __floats2half2_rn(acc.x, acc.y);
            __half2 h1 = __floats2half2_rn(acc.z, acc.w);
            uint2 u;
            u.x = *(unsigned*)&h0; u.y = *(unsigned*)&h1;
            ((uint2*)(yh + (size_t)warp * EMB))[lane] = u;
        }
        float4* orow = (float4*)(out + (size_t)warp * EMB);
        float4 pv = orow[lane];
        pv.x += scale * acc.x; pv.y += scale * acc.y;
        pv.z += scale * acc.z; pv.w += scale * acc.w;
        orow[lane] = pv;
    }
}

// ---------------------------------------------------------------------------
// Launch: inputs are adj_row, adj_col, adj_val, embedding, a
// ---------------------------------------------------------------------------
extern "C" void kernel_launch(void* const* d_in, const int* in_sizes, int n_in,
                              void* d_out, int out_size)
{
    const int*   adj_row = (const int*)  d_in[0];
    const int*   adj_col = (const int*)  d_in[1];
    const float* adj_val = (const float*)d_in[2];
    const float* emb     = (const float*)d_in[3];
    const float* a       = (const float*)d_in[4];
    float*       out     = (float*)d_out;

    __half* embh; cudaGetSymbolAddress((void**)&embh, g_embH);
    __half* bufA; cudaGetSymbolAddress((void**)&bufA, g_bufHA);
    __half* bufB; cudaGetSymbolAddress((void**)&bufB, g_bufHB);
    int*   deg;   cudaGetSymbolAddress((void**)&deg,   g_deg);
    int*   rank;  cudaGetSymbolAddress((void**)&rank,  g_rank);
    int*   rp;    cudaGetSymbolAddress((void**)&rp,    g_rowptr);
    int*   cnt;   cudaGetSymbolAddress((void**)&cnt,   g_counter);
    int2*  cells; cudaGetSymbolAddress((void**)&cells, g_cells);

    const int EB   = (N_EDGES + 255) / 256;
    const int ROWB = (N_NODES * 32 + 255) / 256;
    const int NODB = (N_NODES + 255) / 256;

    // layer 0 + init
    norm0_kernel<<<ROWB, 256>>>(emb, out, embh, a, deg, cnt);
    // CSR build (rank trick: no atomics in scatter)
    hist_rank_kernel<<<EB, 256>>>(adj_row, deg, rank);
    offsets_kernel<<<NODB, 256>>>(deg, rp, cnt);
    scatter_kernel<<<EB, 256>>>(adj_row, adj_col, adj_val, rp, rank, cells);
    // 3 fused SpMM + normalize + accumulate layers
    spmm_fused_kernel<true ><<<ROWB, 256>>>(rp, deg, cells, embh, bufA, out, a, 1);
    spmm_fused_kernel<true ><<<ROWB, 256>>>(rp, deg, cells, bufA, bufB, out, a, 2);
    spmm_fused_kernel<false><<<ROWB, 256>>>(rp, deg, cells, bufB, nullptr, out, a, 3);
}